// round 6
// baseline (speedup 1.0000x reference)
#include <cuda_runtime.h>
#include <cuda_bf16.h>
#include <cstdint>

// Problem constants
#define BATCH 2
#define SEQ   2048
#define DMODEL 4096
#define NHEADS 32
#define NKVH   8
#define HEADD  128
#define REP    4            // NHEADS / NKVH
#define NROWS  (BATCH*SEQ)  // 4096

typedef unsigned long long ull;

// ---------------- scratch (device globals: no runtime allocation) ----------------
__device__ float g_q[(size_t)NROWS * DMODEL];          // (B*L, H*HD)   64 MB
__device__ float g_k[(size_t)NROWS * NKVH * HEADD];    // (B*L, KVH*HD) 16 MB
__device__ float g_v[(size_t)NROWS * NKVH * HEADD];    // 16 MB
__device__ float g_attn[(size_t)NROWS * DMODEL];       // 64 MB

// ---------------- f32x2 packed helpers ----------------
__device__ __forceinline__ ull pk2(float lo, float hi) {
    ull r; asm("mov.b64 %0, {%1,%2};" : "=l"(r) : "f"(lo), "f"(hi)); return r;
}
__device__ __forceinline__ void up2(ull v, float &lo, float &hi) {
    asm("mov.b64 {%0,%1}, %2;" : "=f"(lo), "=f"(hi) : "l"(v));
}
__device__ __forceinline__ ull f2fma(ull a, ull b, ull c) {
    ull d; asm("fma.rn.f32x2 %0, %1, %2, %3;" : "=l"(d) : "l"(a), "l"(b), "l"(c)); return d;
}
__device__ __forceinline__ ull f2mul(ull a, ull b) {
    ull d; asm("mul.rn.f32x2 %0, %1, %2;" : "=l"(d) : "l"(a), "l"(b)); return d;
}

// =================================================================================
// SGEMM: C[M,N] = A[M,K] @ B[K,N], all row-major fp32. 128x128 tile, BK=8,
// 256 threads, 8x8 microtile per thread, f32x2 packed FMA, reg-prefetch.
// Requires M%128==0, N%128==0, K%8==0 (true for all calls here).
// =================================================================================
__global__ void __launch_bounds__(256) sgemm_f32x2(
    const float* __restrict__ A, const float* __restrict__ B,
    float* __restrict__ C, int M, int N, int K)
{
    __shared__ __align__(16) float As[8][132];   // transposed [k][m], stride pad
    __shared__ __align__(16) float Bs[8][128];   // [k][n]

    const int t  = threadIdx.x;
    const int tx = t & 15, ty = t >> 4;
    const int m0 = blockIdx.y << 7, n0 = blockIdx.x << 7;
    const int ty8 = ty << 3, tx8 = tx << 3;

    // A-load: thread -> (row ar, k-offset ak), float4
    const int ar = t >> 1, ak = (t & 1) << 2;
    // B-load: thread -> (k-row bk, n-offset bn), float4
    const int bk = t >> 5, bn = (t & 31) << 2;

    const float* Ap = A + (size_t)(m0 + ar) * K + ak;
    const float* Bp = B + (size_t)bk * N + n0 + bn;

    float4 av = *(const float4*)Ap;
    float4 bv = *(const float4*)Bp;

    ull c2[8][4];
#pragma unroll
    for (int i = 0; i < 8; ++i)
#pragma unroll
        for (int j = 0; j < 4; ++j) c2[i][j] = 0ull;

    for (int k0 = 0; k0 < K; k0 += 8) {
        // stage to smem
        As[ak + 0][ar] = av.x; As[ak + 1][ar] = av.y;
        As[ak + 2][ar] = av.z; As[ak + 3][ar] = av.w;
        *(float4*)&Bs[bk][bn] = bv;
        __syncthreads();

        // prefetch next k-tile into registers (hide LDG latency behind compute)
        if (k0 + 8 < K) {
            av = *(const float4*)(Ap + k0 + 8);
            bv = *(const float4*)(Bp + (size_t)(k0 + 8) * N);
        }

#pragma unroll
        for (int kk = 0; kk < 8; ++kk) {
            float4 a0 = *(const float4*)&As[kk][ty8];
            float4 a1 = *(const float4*)&As[kk][ty8 + 4];
            const float* br = &Bs[kk][tx8];
            ull b0 = *(const ull*)(br + 0);
            ull b1 = *(const ull*)(br + 2);
            ull b2 = *(const ull*)(br + 4);
            ull b3 = *(const ull*)(br + 6);
            float a[8] = {a0.x, a0.y, a0.z, a0.w, a1.x, a1.y, a1.z, a1.w};
#pragma unroll
            for (int i = 0; i < 8; ++i) {
                ull aa = pk2(a[i], a[i]);
                c2[i][0] = f2fma(aa, b0, c2[i][0]);
                c2[i][1] = f2fma(aa, b1, c2[i][1]);
                c2[i][2] = f2fma(aa, b2, c2[i][2]);
                c2[i][3] = f2fma(aa, b3, c2[i][3]);
            }
        }
        __syncthreads();
    }

#pragma unroll
    for (int i = 0; i < 8; ++i) {
        float o[8];
        up2(c2[i][0], o[0], o[1]); up2(c2[i][1], o[2], o[3]);
        up2(c2[i][2], o[4], o[5]); up2(c2[i][3], o[6], o[7]);
        float* cp = C + (size_t)(m0 + ty8 + i) * N + n0 + tx8;
        *(float4*)(cp + 0) = make_float4(o[0], o[1], o[2], o[3]);
        *(float4*)(cp + 4) = make_float4(o[4], o[5], o[6], o[7]);
    }
}

// =================================================================================
// RoPE (interleaved pairs within each head), in-place on (B*L, NH*128) buffer.
// =================================================================================
template <int NH>
__global__ void rope_kernel(float* __restrict__ buf,
                            const float* __restrict__ ct,
                            const float* __restrict__ st, int total)
{
    int idx = blockIdx.x * blockDim.x + threadIdx.x;   // pair index
    if (idx >= total) return;
    int p   = idx & 63;
    int h   = (idx >> 6) & (NH - 1);
    int row = idx / (64 * NH);
    int l   = row & (SEQ - 1);
    float c = ct[(l << 6) + p];
    float s = st[(l << 6) + p];
    float2* ptr = (float2*)(buf + ((size_t)row * NH + h) * HEADD + (p << 1));
    float2 v = *ptr;
    *ptr = make_float2(v.x * c - v.y * s, v.x * s + v.y * c);
}

// =================================================================================
// Flash attention (causal, GQA). BM=BN=64, HD=128.
// Grid (L/64, H, B), 256 threads. 16x16 thread grid:
//   S tile: thread owns rows ty*4..+3, cols tx*4..+3
//   O tile: thread owns rows ty*4..+3, cols tx*8..+7
// Dynamic smem: Qt[128][68], Kt[128][68] (d-major), Vs[64][128], Ps[64][65].
// =================================================================================
#define FA_BM 64
#define FA_BN 64
#define QK_STRIDE 68
#define PS_STRIDE 65
#define FA_SMEM_FLOATS (2 * 128 * QK_STRIDE + FA_BN * 128 + FA_BM * PS_STRIDE)
#define FA_SMEM_BYTES  (FA_SMEM_FLOATS * 4)

__global__ void __launch_bounds__(256) flash_kernel(
    const float* __restrict__ q, const float* __restrict__ k,
    const float* __restrict__ v, float* __restrict__ out)
{
    extern __shared__ __align__(16) float sm[];
    float* Qt = sm;                         // [d][r] stride 68
    float* Kt = Qt + 128 * QK_STRIDE;       // [d][j] stride 68
    float* Vs = Kt + 128 * QK_STRIDE;       // [j][d] stride 128
    float* Ps = Vs + FA_BN * 128;           // [r][j] stride 65

    const int qb = blockIdx.x, h = blockIdx.y, b = blockIdx.z;
    const int kvh = h >> 2;   // REP = 4
    const int t  = threadIdx.x;
    const int tx = t & 15, ty = t >> 4;
    const int ty4 = ty << 2, tx4 = tx << 2, tx8 = tx << 3;
    const float scale = 0.08838834764831845f;   // 1/sqrt(128)

    // ---- load Q tile, transposed + pre-scaled ----
    const float* qbase = q + ((size_t)(b * SEQ + qb * FA_BM)) * DMODEL + h * HEADD;
    for (int i = t; i < FA_BM * 128; i += 256) {
        int r = i >> 7, d = i & 127;
        Qt[d * QK_STRIDE + r] = qbase[(size_t)r * DMODEL + d] * scale;
    }

    float m_i[4], l_i[4];
    ull  o2[4][4];
#pragma unroll
    for (int i = 0; i < 4; ++i) {
        m_i[i] = -1e30f; l_i[i] = 0.0f;
#pragma unroll
        for (int j = 0; j < 4; ++j) o2[i][j] = 0ull;
    }

    for (int kb = 0; kb <= qb; ++kb) {
        __syncthreads();   // prior iter done with Kt/Vs (and Q stores done at kb=0)

        const float* kbase = k + ((size_t)(b * SEQ + kb * FA_BN)) * (NKVH * HEADD) + kvh * HEADD;
        const float* vbase = v + ((size_t)(b * SEQ + kb * FA_BN)) * (NKVH * HEADD) + kvh * HEADD;
        for (int i = t; i < FA_BN * 128; i += 256) {
            int r = i >> 7, d = i & 127;
            Kt[d * QK_STRIDE + r] = kbase[(size_t)r * (NKVH * HEADD) + d];
        }
        for (int i = t; i < FA_BN * 128 / 4; i += 256) {
            int r = i >> 5, c4 = (i & 31) << 2;
            *(float4*)&Vs[r * 128 + c4] = *(const float4*)&vbase[(size_t)r * (NKVH * HEADD) + c4];
        }
        __syncthreads();

        // ---- S = Q K^T (packed f32x2) ----
        ull s2[4][2] = {{0ull,0ull},{0ull,0ull},{0ull,0ull},{0ull,0ull}};
#pragma unroll 8
        for (int d = 0; d < 128; ++d) {
            const float* kr = &Kt[d * QK_STRIDE];
            ull b01 = *(const ull*)(kr + tx4);
            ull b23 = *(const ull*)(kr + tx4 + 2);
            float4 a = *(const float4*)&Qt[d * QK_STRIDE + ty4];
            float av[4] = {a.x, a.y, a.z, a.w};
#pragma unroll
            for (int i = 0; i < 4; ++i) {
                ull aa = pk2(av[i], av[i]);
                s2[i][0] = f2fma(aa, b01, s2[i][0]);
                s2[i][1] = f2fma(aa, b23, s2[i][1]);
            }
        }
        float s[4][4];
#pragma unroll
        for (int i = 0; i < 4; ++i) {
            up2(s2[i][0], s[i][0], s[i][1]);
            up2(s2[i][1], s[i][2], s[i][3]);
        }

        // ---- causal mask on diagonal block ----
        if (kb == qb) {
#pragma unroll
            for (int i = 0; i < 4; ++i)
#pragma unroll
                for (int j = 0; j < 4; ++j)
                    if (tx4 + j > ty4 + i) s[i][j] = -1e30f;
        }

        // ---- online softmax ----
        float p[4][4], rsum[4], alpha[4];
#pragma unroll
        for (int i = 0; i < 4; ++i) {
            float mx = fmaxf(fmaxf(s[i][0], s[i][1]), fmaxf(s[i][2], s[i][3]));
#pragma unroll
            for (int off = 8; off >= 1; off >>= 1)
                mx = fmaxf(mx, __shfl_xor_sync(0xffffffffu, mx, off));
            float mn = fmaxf(m_i[i], mx);
            alpha[i] = __expf(m_i[i] - mn);
            m_i[i] = mn;
            float rs = 0.0f;
#pragma unroll
            for (int j = 0; j < 4; ++j) {
                p[i][j] = __expf(s[i][j] - mn);
                rs += p[i][j];
            }
#pragma unroll
            for (int off = 8; off >= 1; off >>= 1)
                rs += __shfl_xor_sync(0xffffffffu, rs, off);
            rsum[i] = rs;
        }
#pragma unroll
        for (int i = 0; i < 4; ++i) {
            l_i[i] = l_i[i] * alpha[i] + rsum[i];
            ull al2 = pk2(alpha[i], alpha[i]);
#pragma unroll
            for (int j = 0; j < 4; ++j) o2[i][j] = f2mul(o2[i][j], al2);
#pragma unroll
            for (int j = 0; j < 4; ++j) Ps[(ty4 + i) * PS_STRIDE + tx4 + j] = p[i][j];
        }
        __syncthreads();

        // ---- O += P V (packed f32x2) ----
#pragma unroll 4
        for (int j = 0; j < FA_BN; ++j) {
            const float* vr = &Vs[j * 128 + tx8];
            ull v0 = *(const ull*)(vr + 0);
            ull v1 = *(const ull*)(vr + 2);
            ull v2 = *(const ull*)(vr + 4);
            ull v3 = *(const ull*)(vr + 6);
#pragma unroll
            for (int i = 0; i < 4; ++i) {
                float pv = Ps[(ty4 + i) * PS_STRIDE + j];
                ull p2 = pk2(pv, pv);
                o2[i][0] = f2fma(p2, v0, o2[i][0]);
                o2[i][1] = f2fma(p2, v1, o2[i][1]);
                o2[i][2] = f2fma(p2, v2, o2[i][2]);
                o2[i][3] = f2fma(p2, v3, o2[i][3]);
            }
        }
    }

    // ---- epilogue ----
#pragma unroll
    for (int i = 0; i < 4; ++i) {
        float inv = 1.0f / l_i[i];
        float o[8];
        up2(o2[i][0], o[0], o[1]); up2(o2[i][1], o[2], o[3]);
        up2(o2[i][2], o[4], o[5]); up2(o2[i][3], o[6], o[7]);
#pragma unroll
        for (int jj = 0; jj < 8; ++jj) o[jj] *= inv;
        size_t row = (size_t)(b * SEQ + qb * FA_BM + ty4 + i);
        float* op = out + row * DMODEL + h * HEADD + tx8;
        *(float4*)(op + 0) = make_float4(o[0], o[1], o[2], o[3]);
        *(float4*)(op + 4) = make_float4(o[4], o[5], o[6], o[7]);
    }
}

// =================================================================================
// Host launcher
// =================================================================================
extern "C" void kernel_launch(void* const* d_in, const int* in_sizes, int n_in,
                              void* d_out, int out_size)
{
    const float* x   = (const float*)d_in[0];
    const float* wq  = (const float*)d_in[1];
    const float* wk  = (const float*)d_in[2];
    const float* wv  = (const float*)d_in[3];
    const float* wo  = (const float*)d_in[4];
    const float* fcos = (const float*)d_in[5];
    const float* fsin = (const float*)d_in[6];
    // d_in[7] = mask (causal, handled analytically), d_in[8] = start_pos (0)
    float* outp = (float*)d_out;

    float *gq, *gk, *gv, *ga;
    cudaGetSymbolAddress((void**)&gq, g_q);
    cudaGetSymbolAddress((void**)&gk, g_k);
    cudaGetSymbolAddress((void**)&gv, g_v);
    cudaGetSymbolAddress((void**)&ga, g_attn);

    cudaFuncSetAttribute(flash_kernel,
                         cudaFuncAttributeMaxDynamicSharedMemorySize, FA_SMEM_BYTES);

    // QKV projections
    sgemm_f32x2<<<dim3(DMODEL / 128, NROWS / 128), 256>>>(x, wq, gq, NROWS, DMODEL, DMODEL);
    sgemm_f32x2<<<dim3((NKVH * HEADD) / 128, NROWS / 128), 256>>>(x, wk, gk, NROWS, NKVH * HEADD, DMODEL);
    sgemm_f32x2<<<dim3((NKVH * HEADD) / 128, NROWS / 128), 256>>>(x, wv, gv, NROWS, NKVH * HEADD, DMODEL);

    // RoPE on q and k
    {
        int totq = NROWS * NHEADS * 64;
        int totk = NROWS * NKVH * 64;
        rope_kernel<NHEADS><<<(totq + 255) / 256, 256>>>(gq, fcos, fsin, totq);
        rope_kernel<NKVH><<<(totk + 255) / 256, 256>>>(gk, fcos, fsin, totk);
    }

    // Causal flash attention
    flash_kernel<<<dim3(SEQ / FA_BM, NHEADS, BATCH), 256, FA_SMEM_BYTES>>>(gq, gk, gv, ga);

    // Output projection -> d_out
    sgemm_f32x2<<<dim3(DMODEL / 128, NROWS / 128), 256>>>(ga, wo, outp, NROWS, DMODEL, DMODEL);
}